// round 12
// baseline (speedup 1.0000x reference)
#include <cuda_runtime.h>
#include <cuda_fp16.h>
#include <cstdint>

// ---------------- scratch (static __device__ -- no allocation) ----------------
__device__ __half g_Ah[8192 * 256];     // A[(i*32+c)][s]  fp16
__device__ __half g_Bh[8192 * 256];     // B[(j*32+e)][s]  fp16
__device__ __half g_G[67108864];        // G2[(i*256+j)*1024 + c*32 + e] fp16
__device__ float  g_norm[65536];
__device__ __half g_Wth[128 * 1024];    // Wt[z][k] = fp16(w_out[k][z])
__device__ float  g_W12t[64 * 256];     // W'[c64][k] = tf32(lnw[k]*w[k][c]) K-major
__device__ float  g_u[64];
__device__ float  g_vb[64];
__device__ int    g_cnt[128];           // [bi][half] producer counters

#define EPS_MASK 1e-3f
#define LN_EPS   1e-5f

// ------------------------------ helpers ---------------------------------------
__device__ __forceinline__ uint32_t smem_u32(const void* p) {
    uint32_t a;
    asm("{ .reg .u64 t; cvta.to.shared.u64 t, %1; cvt.u32.u64 %0, t; }"
        : "=r"(a) : "l"(p));
    return a;
}
__device__ __forceinline__ float tf32_rn(float x) {
    uint32_t u;
    asm("cvt.rn.tf32.f32 %0, %1;" : "=r"(u) : "f"(x));
    return __uint_as_float(u);
}
__device__ __forceinline__ uint32_t tf32_rn_u(float x) {
    uint32_t u;
    asm("cvt.rn.tf32.f32 %0, %1;" : "=r"(u) : "f"(x));
    return u;
}
__device__ __forceinline__ void cp16(uint32_t saddr, const void* gaddr) {
    asm volatile("cp.async.cg.shared.global [%0], [%1], 16;"
                 :: "r"(saddr), "l"(gaddr) : "memory");
}
#define CP_COMMIT() asm volatile("cp.async.commit_group;" ::: "memory")
#define CP_WAIT0()  asm volatile("cp.async.wait_group 0;" ::: "memory")
#define CP_WAIT1()  asm volatile("cp.async.wait_group 1;" ::: "memory")

__device__ __forceinline__ void mma_tf32(float* d, const uint32_t* a, const uint32_t* b) {
    asm volatile(
        "mma.sync.aligned.m16n8k8.row.col.f32.tf32.tf32.f32 "
        "{%0,%1,%2,%3}, {%4,%5,%6,%7}, {%8,%9}, {%0,%1,%2,%3};"
        : "+f"(d[0]), "+f"(d[1]), "+f"(d[2]), "+f"(d[3])
        : "r"(a[0]), "r"(a[1]), "r"(a[2]), "r"(a[3]), "r"(b[0]), "r"(b[1]));
}
__device__ __forceinline__ void mma_f16(float* d, const uint32_t* a, const uint32_t* b) {
    asm volatile(
        "mma.sync.aligned.m16n8k16.row.col.f32.f16.f16.f32 "
        "{%0,%1,%2,%3}, {%4,%5,%6,%7}, {%8,%9}, {%0,%1,%2,%3};"
        : "+f"(d[0]), "+f"(d[1]), "+f"(d[2]), "+f"(d[3])
        : "r"(a[0]), "r"(a[1]), "r"(a[2]), "r"(a[3]), "r"(b[0]), "r"(b[1]));
}
__device__ __forceinline__ void ldsm_x4(uint32_t* r, uint32_t saddr) {
    asm volatile("ldmatrix.sync.aligned.m8n8.x4.shared.b16 {%0,%1,%2,%3}, [%4];"
                 : "=r"(r[0]), "=r"(r[1]), "=r"(r[2]), "=r"(r[3]) : "r"(saddr));
}
__device__ __forceinline__ void ldsm_x2(uint32_t* r, uint32_t saddr) {
    asm volatile("ldmatrix.sync.aligned.m8n8.x2.shared.b16 {%0,%1}, [%2];"
                 : "=r"(r[0]), "=r"(r[1]) : "r"(saddr));
}

// ---------------- fp16 tile geometry: pitch 72 halves (conflict-free) ----------
#define HPITCH   72
#define ATILE_H  (128 * HPITCH)               // 9216 halves per 128-row tile
#define G_STAGE  (2 * ATILE_H)                // A + B per stage
#define G_SMEM_BYTES (3 * G_STAGE * 2)        // 110592 B (3-stage)

// ---------------- k_prep: norm gram / w_out transpose / LN-fold / cnt reset ----
__global__ void k_prep(const float* __restrict__ mask,
                       const float* __restrict__ w_out,
                       const float* __restrict__ lnw, const float* __restrict__ lnb,
                       const float* __restrict__ w1, const float* __restrict__ b1,
                       const float* __restrict__ w2, const float* __restrict__ b2) {
    int bx = blockIdx.x;
    if (bx < 256) {
        if (bx == 0 && threadIdx.x < 128) g_cnt[threadIdx.x] = 0;
        int i = bx, j = threadIdx.x;
        float acc = EPS_MASK;
        for (int s = 0; s < 256; s++)
            acc += mask[s * 256 + i] * mask[s * 256 + j];
        g_norm[i * 256 + j] = acc;
    } else if (bx < 384) {
        __shared__ float tile[32][33];
        int b2x = bx - 256;
        int kt = (b2x & 31) * 32;
        int zt = (b2x >> 5) * 32;
        int tx = threadIdx.x & 31, ty = threadIdx.x >> 5;
        #pragma unroll
        for (int r = 0; r < 32; r += 8)
            tile[ty + r][tx] = w_out[(size_t)(kt + ty + r) * 128 + zt + tx];
        __syncthreads();
        #pragma unroll
        for (int r = 0; r < 32; r += 8)
            g_Wth[(size_t)(zt + ty + r) * 1024 + kt + tx] = __float2half_rn(tile[tx][ty + r]);
    } else {
        __shared__ float su[256], sv[256];
        int c = bx - 384, k = threadIdx.x;
        int cc = (c < 32) ? c : c - 32;
        const float* w = (c < 32) ? w1 : w2;
        float wv = w[(size_t)k * 32 + cc];
        float wp = lnw[k] * wv;
        g_W12t[c * 256 + k] = tf32_rn(wp);
        su[k] = wp;
        sv[k] = lnb[k] * wv;
        __syncthreads();
        for (int o = 128; o; o >>= 1) {
            if (k < o) { su[k] += su[k + o]; sv[k] += sv[k + o]; }
            __syncthreads();
        }
        if (k == 0) {
            g_u[c]  = su[0];
            g_vb[c] = sv[0] + ((c < 32) ? b1[cc] : b2[cc]);
        }
    }
}

// ---------------- fp32 tile loader for K1 (rows x 32 floats, pitch 36) ---------
#define PITCH 36
template <int ROWS>
__device__ __forceinline__ void load_tile_f(uint32_t sbase, int smoff_floats,
                                            const float* gbase, size_t gpitch,
                                            int ko, int t) {
    #pragma unroll
    for (int q = 0; q < (ROWS * 8) / 256; q++) {
        int cidx = t + q * 256;
        int row  = cidx >> 3;
        int k4   = cidx & 7;
        uint32_t dst = sbase + (uint32_t)(smoff_floats + row * PITCH + k4 * 4) * 4;
        cp16(dst, gbase + (size_t)row * gpitch + ko + k4 * 4);
    }
}

// ---------------- fp16 tile loader (rows x 64 halves, pitch 72) ----------------
template <int ROWS>
__device__ __forceinline__ void load_tile_h(uint32_t sbase, int smoff_halves,
                                            const __half* gbase, size_t gpitch,
                                            int ko, int t) {
    #pragma unroll
    for (int q = 0; q < (ROWS * 8) / 256; q++) {
        int cidx = t + q * 256;
        int row  = cidx >> 3;
        int k8   = cidx & 7;
        uint32_t dst = sbase + (uint32_t)(smoff_halves + row * HPITCH + k8 * 8) * 2;
        cp16(dst, gbase + (size_t)row * gpitch + ko + k8 * 8);
    }
}

// per-lane ldmatrix offsets (bytes):
__device__ __forceinline__ uint32_t ldsm_a_off(int lane) {
    return (uint32_t)((((lane >> 3) & 1) * 8 + (lane & 7)) * (HPITCH * 2)
                      + (lane >> 4) * 16);
}
__device__ __forceinline__ uint32_t ldsm_b_off(int lane) {
    return (uint32_t)((lane & 7) * (HPITCH * 2) + ((lane >> 3) & 1) * 16);
}

// fp16 compute via ldmatrix: one 64-K chunk, 128x128 tile (8 warps 2x4) — round-9
__device__ __forceinline__ void compute_chunk_ldsm(uint32_t As_b, uint32_t Bs_b,
                                                   int wm, int wn,
                                                   uint32_t a_off, uint32_t b_off,
                                                   float acc[4][4][4]) {
    #pragma unroll
    for (int ks = 0; ks < 4; ks++) {
        const uint32_t k0b = (uint32_t)(ks * 16) * 2;
        uint32_t af[4][4], bf[4][2];
        #pragma unroll
        for (int mt = 0; mt < 4; mt++) {
            uint32_t m0 = wm * 64 + mt * 16;
            ldsm_x4(af[mt], As_b + m0 * (HPITCH * 2) + k0b + a_off);
        }
        #pragma unroll
        for (int nt = 0; nt < 4; nt++) {
            uint32_t n0 = wn * 32 + nt * 8;
            ldsm_x2(bf[nt], Bs_b + n0 * (HPITCH * 2) + k0b + b_off);
        }
        #pragma unroll
        for (int mt = 0; mt < 4; mt++)
            #pragma unroll
            for (int nt = 0; nt < 4; nt++)
                mma_f16(acc[mt][nt], af[mt], bf[nt]);
    }
}

// ----- K1: fused LN stats + LN-folded projection GEMM + masked fp16 store ------
#define K1_ATILE (128 * PITCH)
#define K1_BTILE (64 * PITCH)
#define K1_SMEM_BYTES ((2 * K1_ATILE + 2 * K1_BTILE) * 4)
__global__ __launch_bounds__(256) void k1_mma(const float* __restrict__ m,
                                              const float* __restrict__ mask) {
    extern __shared__ float sm[];
    uint32_t sbase = smem_u32(sm);
    const int t = threadIdx.x;
    const int n  = blockIdx.x >> 1;
    const int s0 = (blockIdx.x & 1) * 128;
    const int wid = t >> 5, lane = t & 31;
    const int wm = wid >> 2, wn = wid & 3;
    const int g = lane >> 2, c = lane & 3;

    float acc[4][2][4];
    #pragma unroll
    for (int a = 0; a < 4; a++)
        #pragma unroll
        for (int b = 0; b < 2; b++)
            #pragma unroll
            for (int r = 0; r < 4; r++) acc[a][b][r] = 0.0f;

    float ssum = 0.0f, ssq = 0.0f;
    const int srow = t >> 1;
    const int scol = (t & 1) * 16;

    const float* Agm = m + ((size_t)s0 * 256 + n) * 256;
    const int B_OFF = 2 * K1_ATILE;

    load_tile_f<128>(sbase, 0, Agm, 65536, 0, t);
    load_tile_f<64>(sbase, B_OFF, g_W12t, 256, 0, t);
    CP_COMMIT();

    int buf = 0;
    #pragma unroll 1
    for (int ch = 0; ch < 8; ch++) {
        if (ch + 1 < 8) {
            load_tile_f<128>(sbase, (buf ^ 1) * K1_ATILE, Agm, 65536, (ch + 1) * 32, t);
            load_tile_f<64>(sbase, B_OFF + (buf ^ 1) * K1_BTILE, g_W12t, 256, (ch + 1) * 32, t);
            CP_COMMIT();
            CP_WAIT1();
        } else {
            CP_WAIT0();
        }
        __syncthreads();
        const float* As = sm + buf * K1_ATILE;
        const float* Bs = sm + B_OFF + buf * K1_BTILE;
        #pragma unroll
        for (int kk = 0; kk < 4; kk++) {
            int k0 = kk * 8;
            uint32_t af[4][4], bf[2][2];
            #pragma unroll
            for (int mt = 0; mt < 4; mt++) {
                int m0 = wm * 64 + mt * 16;
                af[mt][0] = tf32_rn_u(As[(m0 + g)     * PITCH + k0 + c]);
                af[mt][1] = tf32_rn_u(As[(m0 + g + 8) * PITCH + k0 + c]);
                af[mt][2] = tf32_rn_u(As[(m0 + g)     * PITCH + k0 + c + 4]);
                af[mt][3] = tf32_rn_u(As[(m0 + g + 8) * PITCH + k0 + c + 4]);
            }
            #pragma unroll
            for (int nt = 0; nt < 2; nt++) {
                int n0 = wn * 16 + nt * 8;
                bf[nt][0] = __float_as_uint(Bs[(n0 + g) * PITCH + k0 + c]);
                bf[nt][1] = __float_as_uint(Bs[(n0 + g) * PITCH + k0 + c + 4]);
            }
            #pragma unroll
            for (int mt = 0; mt < 4; mt++)
                #pragma unroll
                for (int nt = 0; nt < 2; nt++)
                    mma_tf32(acc[mt][nt], af[mt], bf[nt]);
        }
        #pragma unroll
        for (int x = 0; x < 16; x++) {
            float v = As[srow * PITCH + scol + x];
            ssum += v;
            ssq  += v * v;
        }
        __syncthreads();
        buf ^= 1;
    }

    ssum += __shfl_xor_sync(0xFFFFFFFFu, ssum, 1);
    ssq  += __shfl_xor_sync(0xFFFFFFFFu, ssq,  1);
    if ((t & 1) == 0) {
        float mu  = ssum * (1.0f / 256.0f);
        float var = ssq * (1.0f / 256.0f) - mu * mu;
        sm[srow]       = mu;
        sm[128 + srow] = rsqrtf(var + LN_EPS);
    }
    __syncthreads();

    #pragma unroll
    for (int mt = 0; mt < 4; mt++) {
        #pragma unroll
        for (int half = 0; half < 2; half++) {
            int ls = wm * 64 + mt * 16 + g + half * 8;
            int s = s0 + ls;
            float mu = sm[ls], rs = sm[128 + ls];
            float murs = -mu * rs;
            float mval = mask[(size_t)s * 256 + n];
            #pragma unroll
            for (int nt = 0; nt < 2; nt++) {
                #pragma unroll
                for (int x = 0; x < 2; x++) {
                    int ch = wn * 16 + nt * 8 + c * 2 + x;
                    float val = (rs * acc[mt][nt][half * 2 + x]
                                 + murs * g_u[ch] + g_vb[ch]) * mval;
                    __half* buf_out = (ch < 32) ? g_Ah : g_Bh;
                    int cc = ch & 31;
                    buf_out[((size_t)n * 32 + cc) * 256 + s] = __float2half_rn(val);
                }
            }
        }
    }
}

// ---- K23 fused: interleaved producer (G tiles) / consumer (final GEMM) --------
// grid 4608 = 64 groups x (64 k2 blocks + 8 k3 blocks). k3 group g depends only
// on k2 blocks (bi=g, bj half), tracked via g_cnt — G is L2-hot when consumed.
__global__ __launch_bounds__(256, 2) void k23_mma(const float* __restrict__ b_out,
                                                  float* __restrict__ dout) {
    extern __shared__ __half smh[];
    uint32_t sbase = smem_u32(smh);
    const int t = threadIdx.x;
    const int wid = t >> 5, lane = t & 31;
    const int wm = wid >> 2, wn = wid & 3;
    const int g = lane >> 2, c = lane & 3;
    const uint32_t a_off = ldsm_a_off(lane);
    const uint32_t b_off = ldsm_b_off(lane);

    const int grp = blockIdx.x / 72;
    const int loc = blockIdx.x % 72;

    float acc[4][4][4];
    #pragma unroll
    for (int a = 0; a < 4; a++)
        #pragma unroll
        for (int b = 0; b < 4; b++)
            #pragma unroll
            for (int r = 0; r < 4; r++) acc[a][b][r] = 0.0f;

    if (loc < 64) {
        // ---------------- producer: k2 block (bi=grp, bj=loc) ----------------
        const int bi = grp, bj = loc;
        const __half* Agm = g_Ah + (size_t)bi * 128 * 256;
        const __half* Bgm = g_Bh + (size_t)bj * 128 * 256;

        #pragma unroll
        for (int p = 0; p < 2; p++) {
            load_tile_h<128>(sbase, p * G_STAGE, Agm, 256, p * 64, t);
            load_tile_h<128>(sbase, p * G_STAGE + ATILE_H, Bgm, 256, p * 64, t);
            CP_COMMIT();
        }
        #pragma unroll 1
        for (int ch = 0; ch < 4; ch++) {
            if (ch < 2) CP_WAIT1(); else CP_WAIT0();
            __syncthreads();
            if (ch + 2 < 4) {
                int s = (ch + 2) % 3;
                load_tile_h<128>(sbase, s * G_STAGE, Agm, 256, (ch + 2) * 64, t);
                load_tile_h<128>(sbase, s * G_STAGE + ATILE_H, Bgm, 256, (ch + 2) * 64, t);
                CP_COMMIT();
            }
            int s = ch % 3;
            compute_chunk_ldsm(sbase + s * G_STAGE * 2,
                               sbase + (s * G_STAGE + ATILE_H) * 2,
                               wm, wn, a_off, b_off, acc);
        }

        // permuted fp16 store (round-9; every 128B line fully written by block)
        #pragma unroll
        for (int mt = 0; mt < 4; mt++) {
            int rI0 = bi * 128 + wm * 64 + mt * 16;
            #pragma unroll
            for (int half = 0; half < 2; half++) {
                int rI = rI0 + g + half * 8;
                size_t base = ((size_t)(rI >> 5) << 18) + ((size_t)(rI & 31) << 5);
                #pragma unroll
                for (int nt = 0; nt < 4; nt++) {
                    int cJ = bj * 128 + wn * 32 + nt * 8 + c * 2;
                    __half2 v = __floats2half2_rn(acc[mt][nt][half * 2 + 0],
                                                  acc[mt][nt][half * 2 + 1]);
                    *(__half2*)(g_G + base + ((size_t)(cJ >> 5) << 10) + (cJ & 31)) = v;
                }
            }
        }
        // release: all stores visible, then signal
        __syncthreads();
        __threadfence();
        if (t == 0) atomicAdd(&g_cnt[bi * 2 + (bj >> 5)], 1);
    } else {
        // ---------------- consumer: k3 block bm = grp*8 + (loc-64) ------------
        const int bm = grp * 8 + (loc - 64);
        if (t == 0) {
            int idx = grp * 2 + (bm & 1);
            while (atomicAdd(&g_cnt[idx], 0) < 32) __nanosleep(128);
        }
        __syncthreads();   // acquire for whole block

        const __half* Agm = g_G + (size_t)bm * 128 * 1024;
        const __half* Bgm = g_Wth;

        #pragma unroll
        for (int p = 0; p < 2; p++) {
            load_tile_h<128>(sbase, p * G_STAGE, Agm, 1024, p * 64, t);
            load_tile_h<128>(sbase, p * G_STAGE + ATILE_H, Bgm, 1024, p * 64, t);
            CP_COMMIT();
        }
        #pragma unroll 1
        for (int ch = 0; ch < 16; ch++) {
            if (ch < 14) CP_WAIT1(); else CP_WAIT0();
            __syncthreads();
            if (ch + 2 < 16) {
                int s = (ch + 2) % 3;
                load_tile_h<128>(sbase, s * G_STAGE, Agm, 1024, (ch + 2) * 64, t);
                load_tile_h<128>(sbase, s * G_STAGE + ATILE_H, Bgm, 1024, (ch + 2) * 64, t);
                CP_COMMIT();
            }
            int s = ch % 3;
            compute_chunk_ldsm(sbase + s * G_STAGE * 2,
                               sbase + (s * G_STAGE + ATILE_H) * 2,
                               wm, wn, a_off, b_off, acc);
        }

        #pragma unroll
        for (int mt = 0; mt < 4; mt++) {
            #pragma unroll
            for (int half = 0; half < 2; half++) {
                int row = bm * 128 + wm * 64 + mt * 16 + g + half * 8;
                float inv = 1.0f / g_norm[row];
                #pragma unroll
                for (int nt = 0; nt < 4; nt++) {
                    int col = wn * 32 + nt * 8 + c * 2;
                    float2 bo = *(const float2*)(b_out + col);
                    float2 v;
                    v.x = (acc[mt][nt][half * 2 + 0] + bo.x) * inv;
                    v.y = (acc[mt][nt][half * 2 + 1] + bo.y) * inv;
                    *(float2*)(dout + (size_t)row * 128 + col) = v;
                }
            }
        }
    }
}

// ----------------------------------- launch -----------------------------------
extern "C" void kernel_launch(void* const* d_in, const int* in_sizes, int n_in,
                              void* d_out, int out_size)
{
    const float* m     = (const float*)d_in[0];
    const float* mask  = (const float*)d_in[1];
    const float* ln_w  = (const float*)d_in[2];
    const float* ln_b  = (const float*)d_in[3];
    const float* w1    = (const float*)d_in[4];
    const float* b1    = (const float*)d_in[5];
    const float* w2    = (const float*)d_in[6];
    const float* b2    = (const float*)d_in[7];
    const float* w_out = (const float*)d_in[8];
    const float* b_out = (const float*)d_in[9];
    float* out = (float*)d_out;

    cudaFuncSetAttribute(k1_mma, cudaFuncAttributeMaxDynamicSharedMemorySize, K1_SMEM_BYTES);
    cudaFuncSetAttribute(k23_mma, cudaFuncAttributeMaxDynamicSharedMemorySize, G_SMEM_BYTES);

    k_prep<<<448, 256>>>(mask, w_out, ln_w, ln_b, w1, b1, w2, b2);
    k1_mma<<<512, 256, K1_SMEM_BYTES>>>(m, mask);
    k23_mma<<<4608, 256, G_SMEM_BYTES>>>(b_out, out);
}

// round 13
// speedup vs baseline: 1.1818x; 1.1818x over previous
#include <cuda_runtime.h>
#include <cuda_fp16.h>
#include <cstdint>

// ---------------- scratch (static __device__ -- no allocation) ----------------
__device__ __half g_Ah[8192 * 256];     // A[(i*32+c)][s]  fp16
__device__ __half g_Bh[8192 * 256];     // B[(j*32+e)][s]  fp16
__device__ __half g_G[67108864];        // G2[(i*256+j)*1024 + c*32 + e] fp16
__device__ float  g_norm[65536];
__device__ __half g_Wth[128 * 1024];    // Wt[z][k] = fp16(w_out[k][z])
__device__ float  g_W12t[64 * 256];     // W'[c64][k] = tf32(lnw[k]*w[k][c]) K-major
__device__ float  g_u[64];
__device__ float  g_vb[64];

#define EPS_MASK 1e-3f
#define LN_EPS   1e-5f

// ------------------------------ helpers ---------------------------------------
__device__ __forceinline__ uint32_t smem_u32(const void* p) {
    uint32_t a;
    asm("{ .reg .u64 t; cvta.to.shared.u64 t, %1; cvt.u32.u64 %0, t; }"
        : "=r"(a) : "l"(p));
    return a;
}
__device__ __forceinline__ float tf32_rn(float x) {
    uint32_t u;
    asm("cvt.rn.tf32.f32 %0, %1;" : "=r"(u) : "f"(x));
    return __uint_as_float(u);
}
__device__ __forceinline__ uint32_t tf32_rn_u(float x) {
    uint32_t u;
    asm("cvt.rn.tf32.f32 %0, %1;" : "=r"(u) : "f"(x));
    return u;
}
__device__ __forceinline__ void cp16(uint32_t saddr, const void* gaddr) {
    asm volatile("cp.async.cg.shared.global [%0], [%1], 16;"
                 :: "r"(saddr), "l"(gaddr) : "memory");
}
#define CP_COMMIT() asm volatile("cp.async.commit_group;" ::: "memory")
#define CP_WAIT0()  asm volatile("cp.async.wait_group 0;" ::: "memory")
#define CP_WAIT1()  asm volatile("cp.async.wait_group 1;" ::: "memory")

__device__ __forceinline__ void mma_tf32(float* d, const uint32_t* a, const uint32_t* b) {
    asm volatile(
        "mma.sync.aligned.m16n8k8.row.col.f32.tf32.tf32.f32 "
        "{%0,%1,%2,%3}, {%4,%5,%6,%7}, {%8,%9}, {%0,%1,%2,%3};"
        : "+f"(d[0]), "+f"(d[1]), "+f"(d[2]), "+f"(d[3])
        : "r"(a[0]), "r"(a[1]), "r"(a[2]), "r"(a[3]), "r"(b[0]), "r"(b[1]));
}
__device__ __forceinline__ void mma_f16(float* d, const uint32_t* a, const uint32_t* b) {
    asm volatile(
        "mma.sync.aligned.m16n8k16.row.col.f32.f16.f16.f32 "
        "{%0,%1,%2,%3}, {%4,%5,%6,%7}, {%8,%9}, {%0,%1,%2,%3};"
        : "+f"(d[0]), "+f"(d[1]), "+f"(d[2]), "+f"(d[3])
        : "r"(a[0]), "r"(a[1]), "r"(a[2]), "r"(a[3]), "r"(b[0]), "r"(b[1]));
}
__device__ __forceinline__ void ldsm_x4(uint32_t* r, uint32_t saddr) {
    asm volatile("ldmatrix.sync.aligned.m8n8.x4.shared.b16 {%0,%1,%2,%3}, [%4];"
                 : "=r"(r[0]), "=r"(r[1]), "=r"(r[2]), "=r"(r[3]) : "r"(saddr));
}
__device__ __forceinline__ void ldsm_x2(uint32_t* r, uint32_t saddr) {
    asm volatile("ldmatrix.sync.aligned.m8n8.x2.shared.b16 {%0,%1}, [%2];"
                 : "=r"(r[0]), "=r"(r[1]) : "r"(saddr));
}

// ---------------- fp16 tile geometry: pitch 72 halves (conflict-free) ----------
#define HPITCH   72
#define ATILE_H  (128 * HPITCH)               // 9216 halves per 128-row tile
#define G_STAGE  (2 * ATILE_H)                // A + B per stage (k2)
#define G_SMEM_BYTES (3 * G_STAGE * 2)        // 110592 B (3-stage, k2)
// k3: 256-row A tile + 128-row B tile, 2 stages
#define K3_ATILE (256 * HPITCH)               // 18432 halves
#define K3_STAGE (K3_ATILE + ATILE_H)         // 27648 halves
#define K3_SMEM_BYTES (2 * K3_STAGE * 2)      // 110592 B

// ---------------- k_prep: norm gram / w_out transpose / LN-fold ----------------
__global__ void k_prep(const float* __restrict__ mask,
                       const float* __restrict__ w_out,
                       const float* __restrict__ lnw, const float* __restrict__ lnb,
                       const float* __restrict__ w1, const float* __restrict__ b1,
                       const float* __restrict__ w2, const float* __restrict__ b2) {
    int bx = blockIdx.x;
    if (bx < 256) {
        // norm[i][:] : stage column i in smem, 4 independent accumulators
        __shared__ float coli[256];
        int i = bx, j = threadIdx.x;
        coli[j] = mask[j * 256 + i];
        __syncthreads();
        float a0 = EPS_MASK, a1 = 0.f, a2 = 0.f, a3 = 0.f;
        #pragma unroll
        for (int s = 0; s < 256; s += 4) {
            a0 += coli[s + 0] * mask[(s + 0) * 256 + j];
            a1 += coli[s + 1] * mask[(s + 1) * 256 + j];
            a2 += coli[s + 2] * mask[(s + 2) * 256 + j];
            a3 += coli[s + 3] * mask[(s + 3) * 256 + j];
        }
        g_norm[i * 256 + j] = (a0 + a1) + (a2 + a3);
    } else if (bx < 384) {
        __shared__ float tile[32][33];
        int b2x = bx - 256;
        int kt = (b2x & 31) * 32;
        int zt = (b2x >> 5) * 32;
        int tx = threadIdx.x & 31, ty = threadIdx.x >> 5;
        #pragma unroll
        for (int r = 0; r < 32; r += 8)
            tile[ty + r][tx] = w_out[(size_t)(kt + ty + r) * 128 + zt + tx];
        __syncthreads();
        #pragma unroll
        for (int r = 0; r < 32; r += 8)
            g_Wth[(size_t)(zt + ty + r) * 1024 + kt + tx] = __float2half_rn(tile[tx][ty + r]);
    } else {
        __shared__ float su[256], sv[256];
        int c = bx - 384, k = threadIdx.x;
        int cc = (c < 32) ? c : c - 32;
        const float* w = (c < 32) ? w1 : w2;
        float wv = w[(size_t)k * 32 + cc];
        float wp = lnw[k] * wv;
        g_W12t[c * 256 + k] = tf32_rn(wp);
        su[k] = wp;
        sv[k] = lnb[k] * wv;
        __syncthreads();
        for (int o = 128; o; o >>= 1) {
            if (k < o) { su[k] += su[k + o]; sv[k] += sv[k + o]; }
            __syncthreads();
        }
        if (k == 0) {
            g_u[c]  = su[0];
            g_vb[c] = sv[0] + ((c < 32) ? b1[cc] : b2[cc]);
        }
    }
}

// ---------------- fp32 tile loader for K1 (rows x 32 floats, pitch 36) ---------
#define PITCH 36
template <int ROWS>
__device__ __forceinline__ void load_tile_f(uint32_t sbase, int smoff_floats,
                                            const float* gbase, size_t gpitch,
                                            int ko, int t) {
    #pragma unroll
    for (int q = 0; q < (ROWS * 8) / 256; q++) {
        int cidx = t + q * 256;
        int row  = cidx >> 3;
        int k4   = cidx & 7;
        uint32_t dst = sbase + (uint32_t)(smoff_floats + row * PITCH + k4 * 4) * 4;
        cp16(dst, gbase + (size_t)row * gpitch + ko + k4 * 4);
    }
}

// ---------------- fp16 tile loader (rows x 64 halves, pitch 72) ----------------
template <int ROWS, int NTHR>
__device__ __forceinline__ void load_tile_h(uint32_t sbase, int smoff_halves,
                                            const __half* gbase, size_t gpitch,
                                            int ko, int t) {
    #pragma unroll
    for (int q = 0; q < (ROWS * 8) / NTHR; q++) {
        int cidx = t + q * NTHR;
        int row  = cidx >> 3;
        int k8   = cidx & 7;
        uint32_t dst = sbase + (uint32_t)(smoff_halves + row * HPITCH + k8 * 8) * 2;
        cp16(dst, gbase + (size_t)row * gpitch + ko + k8 * 8);
    }
}

// per-lane ldmatrix offsets (bytes):
__device__ __forceinline__ uint32_t ldsm_a_off(int lane) {
    return (uint32_t)((((lane >> 3) & 1) * 8 + (lane & 7)) * (HPITCH * 2)
                      + (lane >> 4) * 16);
}
__device__ __forceinline__ uint32_t ldsm_b_off(int lane) {
    return (uint32_t)((lane & 7) * (HPITCH * 2) + ((lane >> 3) & 1) * 16);
}

// fp16 compute via ldmatrix: one 64-K chunk, 64x32 warp tile (round-9 proven)
__device__ __forceinline__ void compute_chunk_ldsm(uint32_t As_b, uint32_t Bs_b,
                                                   int wm, int wn,
                                                   uint32_t a_off, uint32_t b_off,
                                                   float acc[4][4][4]) {
    #pragma unroll
    for (int ks = 0; ks < 4; ks++) {
        const uint32_t k0b = (uint32_t)(ks * 16) * 2;
        uint32_t af[4][4], bf[4][2];
        #pragma unroll
        for (int mt = 0; mt < 4; mt++) {
            uint32_t m0 = wm * 64 + mt * 16;
            ldsm_x4(af[mt], As_b + m0 * (HPITCH * 2) + k0b + a_off);
        }
        #pragma unroll
        for (int nt = 0; nt < 4; nt++) {
            uint32_t n0 = wn * 32 + nt * 8;
            ldsm_x2(bf[nt], Bs_b + n0 * (HPITCH * 2) + k0b + b_off);
        }
        #pragma unroll
        for (int mt = 0; mt < 4; mt++)
            #pragma unroll
            for (int nt = 0; nt < 4; nt++)
                mma_f16(acc[mt][nt], af[mt], bf[nt]);
    }
}

// ----- K1: fused LN stats + LN-folded projection GEMM + masked fp16 store ------
#define K1_ATILE (128 * PITCH)
#define K1_BTILE (64 * PITCH)
#define K1_SMEM_BYTES ((2 * K1_ATILE + 2 * K1_BTILE) * 4)
__global__ __launch_bounds__(256) void k1_mma(const float* __restrict__ m,
                                              const float* __restrict__ mask) {
    extern __shared__ float sm[];
    uint32_t sbase = smem_u32(sm);
    const int t = threadIdx.x;
    const int n  = blockIdx.x >> 1;
    const int s0 = (blockIdx.x & 1) * 128;
    const int wid = t >> 5, lane = t & 31;
    const int wm = wid >> 2, wn = wid & 3;
    const int g = lane >> 2, c = lane & 3;

    float acc[4][2][4];
    #pragma unroll
    for (int a = 0; a < 4; a++)
        #pragma unroll
        for (int b = 0; b < 2; b++)
            #pragma unroll
            for (int r = 0; r < 4; r++) acc[a][b][r] = 0.0f;

    float ssum = 0.0f, ssq = 0.0f;
    const int srow = t >> 1;
    const int scol = (t & 1) * 16;

    const float* Agm = m + ((size_t)s0 * 256 + n) * 256;
    const int B_OFF = 2 * K1_ATILE;

    load_tile_f<128>(sbase, 0, Agm, 65536, 0, t);
    load_tile_f<64>(sbase, B_OFF, g_W12t, 256, 0, t);
    CP_COMMIT();

    int buf = 0;
    #pragma unroll 1
    for (int ch = 0; ch < 8; ch++) {
        if (ch + 1 < 8) {
            load_tile_f<128>(sbase, (buf ^ 1) * K1_ATILE, Agm, 65536, (ch + 1) * 32, t);
            load_tile_f<64>(sbase, B_OFF + (buf ^ 1) * K1_BTILE, g_W12t, 256, (ch + 1) * 32, t);
            CP_COMMIT();
            CP_WAIT1();
        } else {
            CP_WAIT0();
        }
        __syncthreads();
        const float* As = sm + buf * K1_ATILE;
        const float* Bs = sm + B_OFF + buf * K1_BTILE;
        #pragma unroll
        for (int kk = 0; kk < 4; kk++) {
            int k0 = kk * 8;
            uint32_t af[4][4], bf[2][2];
            #pragma unroll
            for (int mt = 0; mt < 4; mt++) {
                int m0 = wm * 64 + mt * 16;
                af[mt][0] = tf32_rn_u(As[(m0 + g)     * PITCH + k0 + c]);
                af[mt][1] = tf32_rn_u(As[(m0 + g + 8) * PITCH + k0 + c]);
                af[mt][2] = tf32_rn_u(As[(m0 + g)     * PITCH + k0 + c + 4]);
                af[mt][3] = tf32_rn_u(As[(m0 + g + 8) * PITCH + k0 + c + 4]);
            }
            #pragma unroll
            for (int nt = 0; nt < 2; nt++) {
                int n0 = wn * 16 + nt * 8;
                bf[nt][0] = __float_as_uint(Bs[(n0 + g) * PITCH + k0 + c]);
                bf[nt][1] = __float_as_uint(Bs[(n0 + g) * PITCH + k0 + c + 4]);
            }
            #pragma unroll
            for (int mt = 0; mt < 4; mt++)
                #pragma unroll
                for (int nt = 0; nt < 2; nt++)
                    mma_tf32(acc[mt][nt], af[mt], bf[nt]);
        }
        #pragma unroll
        for (int x = 0; x < 16; x++) {
            float v = As[srow * PITCH + scol + x];
            ssum += v;
            ssq  += v * v;
        }
        __syncthreads();
        buf ^= 1;
    }

    ssum += __shfl_xor_sync(0xFFFFFFFFu, ssum, 1);
    ssq  += __shfl_xor_sync(0xFFFFFFFFu, ssq,  1);
    if ((t & 1) == 0) {
        float mu  = ssum * (1.0f / 256.0f);
        float var = ssq * (1.0f / 256.0f) - mu * mu;
        sm[srow]       = mu;
        sm[128 + srow] = rsqrtf(var + LN_EPS);
    }
    __syncthreads();

    #pragma unroll
    for (int mt = 0; mt < 4; mt++) {
        #pragma unroll
        for (int half = 0; half < 2; half++) {
            int ls = wm * 64 + mt * 16 + g + half * 8;
            int s = s0 + ls;
            float mu = sm[ls], rs = sm[128 + ls];
            float murs = -mu * rs;
            float mval = mask[(size_t)s * 256 + n];
            #pragma unroll
            for (int nt = 0; nt < 2; nt++) {
                #pragma unroll
                for (int x = 0; x < 2; x++) {
                    int ch = wn * 16 + nt * 8 + c * 2 + x;
                    float val = (rs * acc[mt][nt][half * 2 + x]
                                 + murs * g_u[ch] + g_vb[ch]) * mval;
                    __half* buf_out = (ch < 32) ? g_Ah : g_Bh;
                    int cc = ch & 31;
                    buf_out[((size_t)n * 32 + cc) * 256 + s] = __float2half_rn(val);
                }
            }
        }
    }
}

// --------- K2: G = A * B^T, ldmatrix + 3-stage pipeline (round-9 champion) -----
__global__ __launch_bounds__(256, 2) void k2_mma() {
    extern __shared__ __half smh[];
    uint32_t sbase = smem_u32(smh);
    const int t = threadIdx.x;
    const int bi = blockIdx.y, bj = blockIdx.x;
    const int wid = t >> 5, lane = t & 31;
    const int wm = wid >> 2, wn = wid & 3;
    const int g = lane >> 2, c = lane & 3;
    const uint32_t a_off = ldsm_a_off(lane);
    const uint32_t b_off = ldsm_b_off(lane);

    float acc[4][4][4];
    #pragma unroll
    for (int a = 0; a < 4; a++)
        #pragma unroll
        for (int b = 0; b < 4; b++)
            #pragma unroll
            for (int r = 0; r < 4; r++) acc[a][b][r] = 0.0f;

    const __half* Agm = g_Ah + (size_t)bi * 128 * 256;
    const __half* Bgm = g_Bh + (size_t)bj * 128 * 256;

    #pragma unroll
    for (int p = 0; p < 2; p++) {
        load_tile_h<128, 256>(sbase, p * G_STAGE, Agm, 256, p * 64, t);
        load_tile_h<128, 256>(sbase, p * G_STAGE + ATILE_H, Bgm, 256, p * 64, t);
        CP_COMMIT();
    }

    #pragma unroll 1
    for (int ch = 0; ch < 4; ch++) {
        if (ch < 2) CP_WAIT1(); else CP_WAIT0();
        __syncthreads();
        if (ch + 2 < 4) {
            int s = (ch + 2) % 3;
            load_tile_h<128, 256>(sbase, s * G_STAGE, Agm, 256, (ch + 2) * 64, t);
            load_tile_h<128, 256>(sbase, s * G_STAGE + ATILE_H, Bgm, 256, (ch + 2) * 64, t);
            CP_COMMIT();
        }
        int s = ch % 3;
        compute_chunk_ldsm(sbase + s * G_STAGE * 2, sbase + (s * G_STAGE + ATILE_H) * 2,
                           wm, wn, a_off, b_off, acc);
    }

    #pragma unroll
    for (int mt = 0; mt < 4; mt++) {
        int rI0 = bi * 128 + wm * 64 + mt * 16;
        #pragma unroll
        for (int half = 0; half < 2; half++) {
            int rI = rI0 + g + half * 8;
            size_t base = ((size_t)(rI >> 5) << 18) + ((size_t)(rI & 31) << 5);
            #pragma unroll
            for (int nt = 0; nt < 4; nt++) {
                int cJ = bj * 128 + wn * 32 + nt * 8 + c * 2;
                __half2 v = __floats2half2_rn(acc[mt][nt][half * 2 + 0],
                                              acc[mt][nt][half * 2 + 1]);
                *(__half2*)(g_G + base + ((size_t)(cJ >> 5) << 10) + (cJ & 31)) = v;
            }
        }
    }
}

// ---- K3: 256x128 block tile, 512 thr (16 warps 4x4 of 64x32), 2-stage ---------
__global__ __launch_bounds__(512) void k3_mma(const float* __restrict__ b_out,
                                              float* __restrict__ dout) {
    extern __shared__ __half smh[];
    uint32_t sbase = smem_u32(smh);
    const int t = threadIdx.x;
    const int bm = blockIdx.x;              // 256-row tile (256 blocks)
    const int wid = t >> 5, lane = t & 31;
    const int wm = wid >> 2, wn = wid & 3;  // 4x4 warp grid
    const int g = lane >> 2, c = lane & 3;
    const uint32_t a_off = ldsm_a_off(lane);
    const uint32_t b_off = ldsm_b_off(lane);

    float acc[4][4][4];
    #pragma unroll
    for (int a = 0; a < 4; a++)
        #pragma unroll
        for (int b = 0; b < 4; b++)
            #pragma unroll
            for (int r = 0; r < 4; r++) acc[a][b][r] = 0.0f;

    const __half* Agm = g_G + (size_t)bm * 256 * 1024;
    const __half* Bgm = g_Wth;

    load_tile_h<256, 512>(sbase, 0, Agm, 1024, 0, t);
    load_tile_h<128, 512>(sbase, K3_ATILE, Bgm, 1024, 0, t);
    CP_COMMIT();

    int buf = 0;
    #pragma unroll 1
    for (int ch = 0; ch < 16; ch++) {
        if (ch + 1 < 16) {
            int s = buf ^ 1;
            load_tile_h<256, 512>(sbase, s * K3_STAGE, Agm, 1024, (ch + 1) * 64, t);
            load_tile_h<128, 512>(sbase, s * K3_STAGE + K3_ATILE, Bgm, 1024, (ch + 1) * 64, t);
            CP_COMMIT();
            CP_WAIT1();
        } else {
            CP_WAIT0();
        }
        __syncthreads();
        compute_chunk_ldsm(sbase + buf * K3_STAGE * 2,
                           sbase + (buf * K3_STAGE + K3_ATILE) * 2,
                           wm, wn, a_off, b_off, acc);
        __syncthreads();
        buf ^= 1;
    }

    #pragma unroll
    for (int mt = 0; mt < 4; mt++) {
        #pragma unroll
        for (int half = 0; half < 2; half++) {
            int row = bm * 256 + wm * 64 + mt * 16 + g + half * 8;
            float inv = 1.0f / g_norm[row];
            #pragma unroll
            for (int nt = 0; nt < 4; nt++) {
                int col = wn * 32 + nt * 8 + c * 2;
                float2 bo = *(const float2*)(b_out + col);
                float2 v;
                v.x = (acc[mt][nt][half * 2 + 0] + bo.x) * inv;
                v.y = (acc[mt][nt][half * 2 + 1] + bo.y) * inv;
                *(float2*)(dout + (size_t)row * 128 + col) = v;
            }
        }
    }
}

// ----------------------------------- launch -----------------------------------
extern "C" void kernel_launch(void* const* d_in, const int* in_sizes, int n_in,
                              void* d_out, int out_size)
{
    const float* m     = (const float*)d_in[0];
    const float* mask  = (const float*)d_in[1];
    const float* ln_w  = (const float*)d_in[2];
    const float* ln_b  = (const float*)d_in[3];
    const float* w1    = (const float*)d_in[4];
    const float* b1    = (const float*)d_in[5];
    const float* w2    = (const float*)d_in[6];
    const float* b2    = (const float*)d_in[7];
    const float* w_out = (const float*)d_in[8];
    const float* b_out = (const float*)d_in[9];
    float* out = (float*)d_out;

    cudaFuncSetAttribute(k1_mma, cudaFuncAttributeMaxDynamicSharedMemorySize, K1_SMEM_BYTES);
    cudaFuncSetAttribute(k2_mma, cudaFuncAttributeMaxDynamicSharedMemorySize, G_SMEM_BYTES);
    cudaFuncSetAttribute(k3_mma, cudaFuncAttributeMaxDynamicSharedMemorySize, K3_SMEM_BYTES);

    k_prep<<<448, 256>>>(mask, w_out, ln_w, ln_b, w1, b1, w2, b2);
    k1_mma<<<512, 256, K1_SMEM_BYTES>>>(m, mask);
    k2_mma<<<dim3(64, 64), 256, G_SMEM_BYTES>>>();
    k3_mma<<<256, 512, K3_SMEM_BYTES>>>(b_out, out);
}